// round 2
// baseline (speedup 1.0000x reference)
#include <cuda_runtime.h>

#define NROWS 4096
#define KDIM  2048
#define MARGIN_F 0.3f

// Scratch (no device allocations allowed in kernel_launch)
__device__ float g_sq[NROWS];
__device__ int   g_ap[NROWS];   // float bits, non-negative -> int compare valid
__device__ int   g_an[NROWS];

// ---------------------------------------------------------------------------
// Kernel 1: squared norms per row + init of ap/an accumulators
// ---------------------------------------------------------------------------
__global__ void __launch_bounds__(256) prep_kernel(const float* __restrict__ x) {
    int row = blockIdx.x;
    const float4* xr = reinterpret_cast<const float4*>(x + (size_t)row * KDIM);
    float s = 0.f;
    for (int i = threadIdx.x; i < KDIM / 4; i += 256) {
        float4 v = xr[i];
        s += v.x * v.x + v.y * v.y + v.z * v.z + v.w * v.w;
    }
    __shared__ float red[8];
    #pragma unroll
    for (int o = 16; o; o >>= 1) s += __shfl_down_sync(0xffffffffu, s, o);
    if ((threadIdx.x & 31) == 0) red[threadIdx.x >> 5] = s;
    __syncthreads();
    if (threadIdx.x == 0) {
        float t = 0.f;
        #pragma unroll
        for (int w = 0; w < 8; w++) t += red[w];
        g_sq[row] = t;
        g_ap[row] = 0;            // dist >= 0, max-acc init
        g_an[row] = 0x7f800000;   // +inf bits,  min-acc init
    }
}

// ---------------------------------------------------------------------------
// Kernel 2: fused symmetric Gram tile -> distance -> hardest pos/neg reduce
// Tile 128x128, BK=16, 256 threads, 8x8 microtile per thread.
// Only tiles with bj >= bi are computed; epilogue scatters to both row
// (i-side) and column (j-side) reductions, exploiting dist symmetry.
// ---------------------------------------------------------------------------
__global__ void __launch_bounds__(256, 2)
dist_kernel(const float* __restrict__ x, const int* __restrict__ tg) {
    int bi = blockIdx.y, bj = blockIdx.x;
    if (bj < bi) return;

    __shared__ float a_s[16][128];
    __shared__ float b_s[16][128];
    __shared__ int s_ap_r[128], s_an_r[128];
    __shared__ int s_ap_c[128], s_an_c[128];

    int tid = threadIdx.x;
    int tx = tid & 15;        // 16 col groups
    int ty = tid >> 4;        // 16 row groups

    float acc[8][8];
    #pragma unroll
    for (int r = 0; r < 8; r++)
        #pragma unroll
        for (int c = 0; c < 8; c++) acc[r][c] = 0.f;

    const float* A = x + (size_t)bi * 128 * KDIM;
    const float* B = x + (size_t)bj * 128 * KDIM;

    for (int kt = 0; kt < KDIM; kt += 16) {
        // cooperative load: 128 rows x 16 cols from each operand (float4)
        #pragma unroll
        for (int s = 0; s < 2; s++) {
            int q   = tid + s * 256;   // 0..511
            int row = q >> 2;          // 0..127
            int c4  = (q & 3) * 4;     // 0,4,8,12
            float4 va = *reinterpret_cast<const float4*>(A + (size_t)row * KDIM + kt + c4);
            float4 vb = *reinterpret_cast<const float4*>(B + (size_t)row * KDIM + kt + c4);
            a_s[c4 + 0][row] = va.x; a_s[c4 + 1][row] = va.y;
            a_s[c4 + 2][row] = va.z; a_s[c4 + 3][row] = va.w;
            b_s[c4 + 0][row] = vb.x; b_s[c4 + 1][row] = vb.y;
            b_s[c4 + 2][row] = vb.z; b_s[c4 + 3][row] = vb.w;
        }
        __syncthreads();

        #pragma unroll
        for (int k = 0; k < 16; k++) {
            float ar[8], br[8];
            *reinterpret_cast<float4*>(&ar[0]) = *reinterpret_cast<float4*>(&a_s[k][ty * 8]);
            *reinterpret_cast<float4*>(&ar[4]) = *reinterpret_cast<float4*>(&a_s[k][ty * 8 + 4]);
            *reinterpret_cast<float4*>(&br[0]) = *reinterpret_cast<float4*>(&b_s[k][tx * 8]);
            *reinterpret_cast<float4*>(&br[4]) = *reinterpret_cast<float4*>(&b_s[k][tx * 8 + 4]);
            #pragma unroll
            for (int r = 0; r < 8; r++)
                #pragma unroll
                for (int c = 0; c < 8; c++)
                    acc[r][c] = fmaf(ar[r], br[c], acc[r][c]);
        }
        __syncthreads();
    }

    // epilogue: distance + masked hardest pos/neg, block-level reduction
    if (tid < 128) {
        s_ap_r[tid] = 0; s_an_r[tid] = 0x7f800000;
        s_ap_c[tid] = 0; s_an_c[tid] = 0x7f800000;
    }
    __syncthreads();

    int row0 = bi * 128 + ty * 8;
    int col0 = bj * 128 + tx * 8;
    float sqi[8], sqj[8];
    int li[8], lj[8];
    #pragma unroll
    for (int r = 0; r < 8; r++) { sqi[r] = g_sq[row0 + r]; li[r] = tg[row0 + r]; }
    #pragma unroll
    for (int c = 0; c < 8; c++) { sqj[c] = g_sq[col0 + c]; lj[c] = tg[col0 + c]; }

    const float INF = __int_as_float(0x7f800000);
    float apc[8], anc[8];
    #pragma unroll
    for (int c = 0; c < 8; c++) { apc[c] = 0.f; anc[c] = INF; }

    #pragma unroll
    for (int r = 0; r < 8; r++) {
        float apr = 0.f, anr = INF;
        #pragma unroll
        for (int c = 0; c < 8; c++) {
            float d2 = sqi[r] + sqj[c] - 2.f * acc[r][c];
            float d  = sqrtf(fmaxf(d2, 1e-12f));
            if (li[r] == lj[c]) {
                apr    = fmaxf(apr, d);
                apc[c] = fmaxf(apc[c], d);
            } else {
                anr    = fminf(anr, d);
                anc[c] = fminf(anc[c], d);
            }
        }
        atomicMax(&s_ap_r[ty * 8 + r], __float_as_int(apr));
        atomicMin(&s_an_r[ty * 8 + r], __float_as_int(anr));
    }
    #pragma unroll
    for (int c = 0; c < 8; c++) {
        atomicMax(&s_ap_c[tx * 8 + c], __float_as_int(apc[c]));
        atomicMin(&s_an_c[tx * 8 + c], __float_as_int(anc[c]));
    }
    __syncthreads();

    if (tid < 128) {
        atomicMax(&g_ap[bi * 128 + tid], s_ap_r[tid]);
        atomicMin(&g_an[bi * 128 + tid], s_an_r[tid]);
        atomicMax(&g_ap[bj * 128 + tid], s_ap_c[tid]);
        atomicMin(&g_an[bj * 128 + tid], s_an_c[tid]);
    }
}

// ---------------------------------------------------------------------------
// Kernel 3: loss = mean(relu(margin + ap - an))
// ---------------------------------------------------------------------------
__global__ void __launch_bounds__(256) loss_kernel(float* __restrict__ out) {
    float s = 0.f;
    for (int i = threadIdx.x; i < NROWS; i += 256) {
        float ap = __int_as_float(g_ap[i]);
        float an = __int_as_float(g_an[i]);
        s += fmaxf(MARGIN_F + ap - an, 0.f);
    }
    __shared__ float red[8];
    #pragma unroll
    for (int o = 16; o; o >>= 1) s += __shfl_down_sync(0xffffffffu, s, o);
    if ((threadIdx.x & 31) == 0) red[threadIdx.x >> 5] = s;
    __syncthreads();
    if (threadIdx.x == 0) {
        float t = 0.f;
        #pragma unroll
        for (int w = 0; w < 8; w++) t += red[w];
        out[0] = t / (float)NROWS;
    }
}

extern "C" void kernel_launch(void* const* d_in, const int* in_sizes, int n_in,
                              void* d_out, int out_size) {
    const float* x  = (const float*)d_in[0];
    const int*   tg = (const int*)d_in[1];
    float* out = (float*)d_out;

    prep_kernel<<<NROWS, 256>>>(x);
    dim3 grid(NROWS / 128, NROWS / 128);   // 32 x 32, upper triangle active
    dist_kernel<<<grid, 256>>>(x, tg);
    loss_kernel<<<1, 256>>>(out);
}

// round 4
// speedup vs baseline: 3.5900x; 3.5900x over previous
#include <cuda_runtime.h>
#include <cstdint>

#define NROWS 4096
#define KDIM  2048
#define MARGIN_F 0.3f

#define TM 128            // CTA tile M
#define TN 256            // CTA tile N
#define KC 32             // K chunk
#define NCHUNK (KDIM / KC)   // 64
#define SA 36             // padded smem row stride (words)
#define A_WORDS (TM * SA)    // 4608
#define B_WORDS (TN * SA)    // 9216
#define STAGE_WORDS (A_WORDS + B_WORDS)   // 13824
#define DYN_BYTES (2 * STAGE_WORDS * 4)   // 110592

__device__ float g_sq[NROWS];
__device__ int   g_ap[NROWS];   // d^2 bits (non-negative) -> int max valid
__device__ int   g_an[NROWS];

static __device__ __forceinline__ uint32_t smem_u32(const void* p) {
    uint32_t a;
    asm("{ .reg .u64 t; cvta.to.shared.u64 t, %1; cvt.u32.u64 %0, t; }" : "=r"(a) : "l"(p));
    return a;
}
static __device__ __forceinline__ void cp16(uint32_t s, const void* g) {
    asm volatile("cp.async.cg.shared.global [%0], [%1], 16;" :: "r"(s), "l"(g));
}
#define CP_COMMIT() asm volatile("cp.async.commit_group;" ::: "memory")
#define CP_WAIT1()  asm volatile("cp.async.wait_group 1;" ::: "memory")

static __device__ __forceinline__ void mma_tf32(float* d, const uint32_t* a, const uint32_t* b) {
    asm volatile(
        "mma.sync.aligned.m16n8k8.row.col.f32.tf32.tf32.f32 "
        "{%0,%1,%2,%3}, {%4,%5,%6,%7}, {%8,%9}, {%0,%1,%2,%3};"
        : "+f"(d[0]), "+f"(d[1]), "+f"(d[2]), "+f"(d[3])
        : "r"(a[0]), "r"(a[1]), "r"(a[2]), "r"(a[3]), "r"(b[0]), "r"(b[1]));
}

// ---------------------------------------------------------------------------
// Kernel 1: squared norms per row + init of ap/an accumulators
// ---------------------------------------------------------------------------
__global__ void __launch_bounds__(256) prep_kernel(const float* __restrict__ x) {
    int row = blockIdx.x;
    const float4* xr = reinterpret_cast<const float4*>(x + (size_t)row * KDIM);
    float s = 0.f;
    for (int i = threadIdx.x; i < KDIM / 4; i += 256) {
        float4 v = xr[i];
        s += v.x * v.x + v.y * v.y + v.z * v.z + v.w * v.w;
    }
    __shared__ float red[8];
    #pragma unroll
    for (int o = 16; o; o >>= 1) s += __shfl_down_sync(0xffffffffu, s, o);
    if ((threadIdx.x & 31) == 0) red[threadIdx.x >> 5] = s;
    __syncthreads();
    if (threadIdx.x == 0) {
        float t = 0.f;
        #pragma unroll
        for (int w = 0; w < 8; w++) t += red[w];
        g_sq[row] = t;
        g_ap[row] = 0;
        g_an[row] = 0x7f800000;
    }
}

// ---------------------------------------------------------------------------
// Kernel 2: tf32 mma.sync Gram tile (128x256) -> d^2 -> hardest pos/neg
// Upper-triangle tiles only; epilogue scatters row-side and col-side
// (idempotent max/min -> diagonal-straddle overlap harmless).
// ---------------------------------------------------------------------------
__global__ void __launch_bounds__(256, 1)
dist_kernel(const float* __restrict__ x, const int* __restrict__ tg) {
    int bi = blockIdx.y, bj = blockIdx.x;
    if (bj < (bi >> 1)) return;   // tile fully below diagonal

    extern __shared__ float ds[];
    __shared__ int   s_ap_r[TM], s_an_r[TM];
    __shared__ int   s_ap_c[TN], s_an_c[TN];
    __shared__ float s_sqi[TM],  s_sqj[TN];
    __shared__ int   s_li[TM],   s_lj[TN];

    int tid = threadIdx.x, lid = tid & 31, wid = tid >> 5;
    int wm = wid >> 2, wn = wid & 3;       // 2 x 4 warp grid
    int u = lid >> 2, v = lid & 3;

    const float* Ab = x + (size_t)(bi * TM) * KDIM;
    const float* Bb = x + (size_t)(bj * TN) * KDIM;
    uint32_t sbase = smem_u32(ds);

    if (tid < TM) {
        s_ap_r[tid] = 0; s_an_r[tid] = 0x7f800000;
        s_sqi[tid] = g_sq[bi * TM + tid];
        s_li[tid]  = tg[bi * TM + tid];
    }
    {
        s_ap_c[tid] = 0; s_an_c[tid] = 0x7f800000;
        s_sqj[tid] = g_sq[bj * TN + tid];
        s_lj[tid]  = tg[bj * TN + tid];
    }

    float acc[4][8][4];
    #pragma unroll
    for (int mt = 0; mt < 4; mt++)
        #pragma unroll
        for (int nt = 0; nt < 8; nt++)
            #pragma unroll
            for (int r = 0; r < 4; r++) acc[mt][nt][r] = 0.f;

    // ---- staging: chunk ic -> buffer b via cp.async ----
    #define STAGE(ic, b) do {                                                  \
        uint32_t as_ = sbase + (uint32_t)(b) * (STAGE_WORDS * 4);              \
        uint32_t bs_ = as_ + A_WORDS * 4;                                      \
        const float* Ak_ = Ab + (ic) * KC;                                     \
        const float* Bk_ = Bb + (ic) * KC;                                     \
        _Pragma("unroll")                                                      \
        for (int t = 0; t < 4; t++) {                                          \
            int idx = tid + t * 256; int r = idx >> 3, c4 = idx & 7;           \
            cp16(as_ + (uint32_t)(r * SA + c4 * 4) * 4,                        \
                 Ak_ + (size_t)r * KDIM + c4 * 4);                             \
        }                                                                      \
        _Pragma("unroll")                                                      \
        for (int t = 0; t < 8; t++) {                                          \
            int idx = tid + t * 256; int r = idx >> 3, c4 = idx & 7;           \
            cp16(bs_ + (uint32_t)(r * SA + c4 * 4) * 4,                        \
                 Bk_ + (size_t)r * KDIM + c4 * 4);                             \
        }                                                                      \
    } while (0)

    STAGE(0, 0); CP_COMMIT();
    STAGE(1, 1); CP_COMMIT();

    for (int ic = 0; ic < NCHUNK; ic++) {
        int b = ic & 1;
        CP_WAIT1();
        __syncthreads();

        const float* As = ds + b * STAGE_WORDS + (wm * 64) * SA;
        const float* Bs = ds + b * STAGE_WORDS + A_WORDS + (wn * 64) * SA;

        #pragma unroll
        for (int kk = 0; kk < 4; kk++) {
            int c = kk * 8 + v;
            uint32_t af[4][4], bf[8][2];
            #pragma unroll
            for (int mt = 0; mt < 4; mt++) {
                int r0 = mt * 16 + u;
                af[mt][0] = __float_as_uint(As[r0 * SA + c]);
                af[mt][1] = __float_as_uint(As[(r0 + 8) * SA + c]);
                af[mt][2] = __float_as_uint(As[r0 * SA + c + 4]);
                af[mt][3] = __float_as_uint(As[(r0 + 8) * SA + c + 4]);
            }
            #pragma unroll
            for (int nt = 0; nt < 8; nt++) {
                int n = nt * 8 + u;
                bf[nt][0] = __float_as_uint(Bs[n * SA + c]);
                bf[nt][1] = __float_as_uint(Bs[n * SA + c + 4]);
            }
            #pragma unroll
            for (int mt = 0; mt < 4; mt++)
                #pragma unroll
                for (int nt = 0; nt < 8; nt++)
                    mma_tf32(acc[mt][nt], af[mt], bf[nt]);
        }
        __syncthreads();
        if (ic + 2 < NCHUNK) STAGE(ic + 2, b);
        CP_COMMIT();
    }

    // ---- epilogue: d^2, masked hardest pos/neg, idempotent reductions ----
    const float INF = __int_as_float(0x7f800000);
    float ap_r[8], an_r[8], ap_c[16], an_c[16];
    #pragma unroll
    for (int i = 0; i < 8; i++)  { ap_r[i] = 0.f; an_r[i] = INF; }
    #pragma unroll
    for (int i = 0; i < 16; i++) { ap_c[i] = 0.f; an_c[i] = INF; }

    #pragma unroll
    for (int mt = 0; mt < 4; mt++) {
        #pragma unroll
        for (int rh = 0; rh < 2; rh++) {
            int ml = wm * 64 + mt * 16 + u + rh * 8;
            float sqi = s_sqi[ml];
            int   li  = s_li[ml];
            float apv = ap_r[mt * 2 + rh], anv = an_r[mt * 2 + rh];
            #pragma unroll
            for (int nt = 0; nt < 8; nt++) {
                #pragma unroll
                for (int cb = 0; cb < 2; cb++) {
                    int nl = wn * 64 + nt * 8 + v * 2 + cb;
                    float d2 = fmaxf(fmaf(-2.f, acc[mt][nt][rh * 2 + cb],
                                          sqi + s_sqj[nl]), 0.f);
                    int ci = nt * 2 + cb;
                    if (li == s_lj[nl]) {
                        apv = fmaxf(apv, d2);
                        ap_c[ci] = fmaxf(ap_c[ci], d2);
                    } else {
                        anv = fminf(anv, d2);
                        an_c[ci] = fminf(an_c[ci], d2);
                    }
                }
            }
            ap_r[mt * 2 + rh] = apv; an_r[mt * 2 + rh] = anv;
        }
    }

    const unsigned FM = 0xffffffffu;
    #pragma unroll
    for (int i = 0; i < 8; i++) {
        float ap = ap_r[i], an = an_r[i];
        ap = fmaxf(ap, __shfl_xor_sync(FM, ap, 1));
        ap = fmaxf(ap, __shfl_xor_sync(FM, ap, 2));
        an = fminf(an, __shfl_xor_sync(FM, an, 1));
        an = fminf(an, __shfl_xor_sync(FM, an, 2));
        if (v == 0) {
            int ml = wm * 64 + (i >> 1) * 16 + u + (i & 1) * 8;
            atomicMax(&s_ap_r[ml], __float_as_int(ap));
            atomicMin(&s_an_r[ml], __float_as_int(an));
        }
    }
    #pragma unroll
    for (int i = 0; i < 16; i++) {
        float ap = ap_c[i], an = an_c[i];
        ap = fmaxf(ap, __shfl_xor_sync(FM, ap, 4));
        ap = fmaxf(ap, __shfl_xor_sync(FM, ap, 8));
        ap = fmaxf(ap, __shfl_xor_sync(FM, ap, 16));
        an = fminf(an, __shfl_xor_sync(FM, an, 4));
        an = fminf(an, __shfl_xor_sync(FM, an, 8));
        an = fminf(an, __shfl_xor_sync(FM, an, 16));
        if (u == 0) {
            int nl = wn * 64 + (i >> 1) * 8 + v * 2 + (i & 1);
            atomicMax(&s_ap_c[nl], __float_as_int(ap));
            atomicMin(&s_an_c[nl], __float_as_int(an));
        }
    }
    __syncthreads();

    if (tid < TM) {
        atomicMax(&g_ap[bi * TM + tid], s_ap_r[tid]);
        atomicMin(&g_an[bi * TM + tid], s_an_r[tid]);
    }
    {
        atomicMax(&g_ap[bj * TN + tid], s_ap_c[tid]);
        atomicMin(&g_an[bj * TN + tid], s_an_c[tid]);
    }
}

// ---------------------------------------------------------------------------
// Kernel 3: loss = mean(relu(margin + sqrt(ap2) - sqrt(an2)))
// ---------------------------------------------------------------------------
__global__ void __launch_bounds__(256) loss_kernel(float* __restrict__ out) {
    float s = 0.f;
    for (int i = threadIdx.x; i < NROWS; i += 256) {
        float ap = sqrtf(fmaxf(__int_as_float(g_ap[i]), 1e-12f));
        float an = sqrtf(fmaxf(__int_as_float(g_an[i]), 1e-12f));
        s += fmaxf(MARGIN_F + ap - an, 0.f);
    }
    __shared__ float red[8];
    #pragma unroll
    for (int o = 16; o; o >>= 1) s += __shfl_down_sync(0xffffffffu, s, o);
    if ((threadIdx.x & 31) == 0) red[threadIdx.x >> 5] = s;
    __syncthreads();
    if (threadIdx.x == 0) {
        float t = 0.f;
        #pragma unroll
        for (int w = 0; w < 8; w++) t += red[w];
        out[0] = t / (float)NROWS;
    }
}

extern "C" void kernel_launch(void* const* d_in, const int* in_sizes, int n_in,
                              void* d_out, int out_size) {
    const float* x  = (const float*)d_in[0];
    const int*   tg = (const int*)d_in[1];
    float* out = (float*)d_out;

    cudaFuncSetAttribute(dist_kernel, cudaFuncAttributeMaxDynamicSharedMemorySize, DYN_BYTES);

    prep_kernel<<<NROWS, 256>>>(x);
    dim3 grid(NROWS / TN, NROWS / TM);   // (16, 32): x=bj, y=bi
    dist_kernel<<<grid, 256, DYN_BYTES>>>(x, tg);
    loss_kernel<<<1, 256>>>(out);
}

// round 5
// speedup vs baseline: 4.1426x; 1.1539x over previous
#include <cuda_runtime.h>
#include <cstdint>

#define NROWS 4096
#define KDIM  2048
#define MARGIN_F 0.3f

#define TM 128
#define TN 256
#define KC 32
#define NCHUNK (KDIM / KC)          // 64
#define NTHREADS 512

#define A_BYTES (TM * KC * 4)       // 16384
#define B_BYTES (TN * KC * 4)       // 32768
#define STAGE_BYTES (A_BYTES + B_BYTES)   // 49152
#define NSTAGE 4
#define DYN_BYTES (NSTAGE * STAGE_BYTES + 1024)  // 197632 (incl. align slack)

__device__ float g_sq[NROWS];
__device__ int   g_ap[NROWS];   // d^2 bits (non-negative) -> int max/min valid
__device__ int   g_an[NROWS];

static __device__ __forceinline__ uint32_t smem_u32(const void* p) {
    uint32_t a;
    asm("{ .reg .u64 t; cvta.to.shared.u64 t, %1; cvt.u32.u64 %0, t; }" : "=r"(a) : "l"(p));
    return a;
}
static __device__ __forceinline__ void cp16(uint32_t s, const void* g) {
    asm volatile("cp.async.cg.shared.global [%0], [%1], 16;" :: "r"(s), "l"(g));
}
#define CP_COMMIT() asm volatile("cp.async.commit_group;" ::: "memory")
#define CP_WAIT2()  asm volatile("cp.async.wait_group 2;" ::: "memory")

static __device__ __forceinline__ void mma_tf32(float* d, const uint32_t* a, const uint32_t* b) {
    asm volatile(
        "mma.sync.aligned.m16n8k8.row.col.f32.tf32.tf32.f32 "
        "{%0,%1,%2,%3}, {%4,%5,%6,%7}, {%8,%9}, {%0,%1,%2,%3};"
        : "+f"(d[0]), "+f"(d[1]), "+f"(d[2]), "+f"(d[3])
        : "r"(a[0]), "r"(a[1]), "r"(a[2]), "r"(a[3]), "r"(b[0]), "r"(b[1]));
}

// ---------------------------------------------------------------------------
// Kernel 1: squared norms per row + init of ap/an accumulators
// ---------------------------------------------------------------------------
__global__ void __launch_bounds__(256) prep_kernel(const float* __restrict__ x) {
    int row = blockIdx.x;
    const float4* xr = reinterpret_cast<const float4*>(x + (size_t)row * KDIM);
    float s = 0.f;
    for (int i = threadIdx.x; i < KDIM / 4; i += 256) {
        float4 v = xr[i];
        s += v.x * v.x + v.y * v.y + v.z * v.z + v.w * v.w;
    }
    __shared__ float red[8];
    #pragma unroll
    for (int o = 16; o; o >>= 1) s += __shfl_down_sync(0xffffffffu, s, o);
    if ((threadIdx.x & 31) == 0) red[threadIdx.x >> 5] = s;
    __syncthreads();
    if (threadIdx.x == 0) {
        float t = 0.f;
        #pragma unroll
        for (int w = 0; w < 8; w++) t += red[w];
        g_sq[row] = t;
        g_ap[row] = 0;
        g_an[row] = 0x7f800000;
    }
}

// ---------------------------------------------------------------------------
// Kernel 2: tf32 mma.sync Gram tile (128x256), 16 warps, 4-stage cp.async
// pipeline with XOR-swizzled smem. Upper-triangle tiles only; epilogue
// compares d^2 (sqrt deferred), scatters row- and col-side reductions.
// ---------------------------------------------------------------------------
__global__ void __launch_bounds__(NTHREADS, 1)
dist_kernel(const float* __restrict__ x, const int* __restrict__ tg) {
    int bi = blockIdx.y, bj = blockIdx.x;
    if (bj < (bi >> 1)) return;   // tile fully below diagonal

    extern __shared__ char raw_dsm[];
    __shared__ int   s_ap_r[TM], s_an_r[TM];
    __shared__ int   s_ap_c[TN], s_an_c[TN];
    __shared__ float s_sqi[TM],  s_sqj[TN];
    __shared__ int   s_li[TM],   s_lj[TN];

    int tid = threadIdx.x, lid = tid & 31, wid = tid >> 5;
    int wm = wid >> 3, wn = wid & 7;       // 2 x 8 warp grid, warp tile 64x32
    int u = lid >> 2, v = lid & 3;

    // 1024-align dynamic base for clean swizzle/bank math
    uint32_t raw_base = smem_u32(raw_dsm);
    uint32_t sbase = (raw_base + 1023u) & ~1023u;
    char* ds = raw_dsm + (sbase - raw_base);

    const float* Ab = x + (size_t)(bi * TM) * KDIM;
    const float* Bb = x + (size_t)(bj * TN) * KDIM;

    if (tid < TM) {
        s_ap_r[tid] = 0; s_an_r[tid] = 0x7f800000;
        s_sqi[tid] = g_sq[bi * TM + tid];
        s_li[tid]  = tg[bi * TM + tid];
    }
    if (tid < TN) {
        s_ap_c[tid] = 0; s_an_c[tid] = 0x7f800000;
        s_sqj[tid] = g_sq[bj * TN + tid];
        s_lj[tid]  = tg[bj * TN + tid];
    }

    float acc[4][4][4];
    #pragma unroll
    for (int mt = 0; mt < 4; mt++)
        #pragma unroll
        for (int nt = 0; nt < 4; nt++)
            #pragma unroll
            for (int r = 0; r < 4; r++) acc[mt][nt][r] = 0.f;

    // swizzled 16B-unit staging: byte = r*128 + ((c4*16) ^ ((r&7)*16))
    #define STAGE(ic, s) do {                                                  \
        uint32_t b0_ = sbase + (uint32_t)(s) * STAGE_BYTES;                    \
        const float* Ak_ = Ab + (ic) * KC;                                     \
        const float* Bk_ = Bb + (ic) * KC;                                     \
        _Pragma("unroll")                                                      \
        for (int t = 0; t < 2; t++) {                                          \
            int idx = tid + t * NTHREADS; int r = idx >> 3, c4 = idx & 7;      \
            uint32_t sw = (uint32_t)(r * 128 + ((c4 * 16) ^ ((r & 7) * 16)));  \
            cp16(b0_ + sw, Ak_ + (size_t)r * KDIM + c4 * 4);                   \
        }                                                                      \
        _Pragma("unroll")                                                      \
        for (int t = 0; t < 4; t++) {                                          \
            int idx = tid + t * NTHREADS; int r = idx >> 3, c4 = idx & 7;      \
            uint32_t sw = (uint32_t)(r * 128 + ((c4 * 16) ^ ((r & 7) * 16)));  \
            cp16(b0_ + A_BYTES + sw, Bk_ + (size_t)r * KDIM + c4 * 4);         \
        }                                                                      \
    } while (0)

    STAGE(0, 0); CP_COMMIT();
    STAGE(1, 1); CP_COMMIT();
    STAGE(2, 2); CP_COMMIT();

    for (int ic = 0; ic < NCHUNK; ic++) {
        int s = ic & 3;
        CP_WAIT2();
        __syncthreads();

        const char* As = ds + s * STAGE_BYTES + (wm * 64) * 128;
        const char* Bs = ds + s * STAGE_BYTES + A_BYTES + (wn * 32) * 128;

        #pragma unroll
        for (int kk = 0; kk < 4; kk++) {
            int cx0 = (kk * 32 + v * 4) ^ (u * 16);
            int cx1 = (kk * 32 + 16 + v * 4) ^ (u * 16);
            uint32_t af[4][4], bf[4][2];
            #pragma unroll
            for (int mt = 0; mt < 4; mt++) {
                int r0 = (mt * 16 + u) * 128;
                af[mt][0] = *reinterpret_cast<const uint32_t*>(As + r0 + cx0);
                af[mt][1] = *reinterpret_cast<const uint32_t*>(As + r0 + 1024 + cx0);
                af[mt][2] = *reinterpret_cast<const uint32_t*>(As + r0 + cx1);
                af[mt][3] = *reinterpret_cast<const uint32_t*>(As + r0 + 1024 + cx1);
            }
            #pragma unroll
            for (int nt = 0; nt < 4; nt++) {
                int n0 = (nt * 8 + u) * 128;
                bf[nt][0] = *reinterpret_cast<const uint32_t*>(Bs + n0 + cx0);
                bf[nt][1] = *reinterpret_cast<const uint32_t*>(Bs + n0 + cx1);
            }
            #pragma unroll
            for (int mt = 0; mt < 4; mt++)
                #pragma unroll
                for (int nt = 0; nt < 4; nt++)
                    mma_tf32(acc[mt][nt], af[mt], bf[nt]);
        }

        if (ic + 3 < NCHUNK) STAGE(ic + 3, (ic + 3) & 3);
        CP_COMMIT();
    }

    // ---- epilogue: d^2, masked hardest pos/neg, idempotent reductions ----
    const float INF = __int_as_float(0x7f800000);
    float ap_r[8], an_r[8], ap_c[8], an_c[8];
    #pragma unroll
    for (int i = 0; i < 8; i++) { ap_r[i] = 0.f; an_r[i] = INF; ap_c[i] = 0.f; an_c[i] = INF; }

    #pragma unroll
    for (int mt = 0; mt < 4; mt++) {
        #pragma unroll
        for (int rh = 0; rh < 2; rh++) {
            int ml = wm * 64 + mt * 16 + u + rh * 8;
            float sqi = s_sqi[ml];
            int   li  = s_li[ml];
            int ri = mt * 2 + rh;
            float apv = ap_r[ri], anv = an_r[ri];
            #pragma unroll
            for (int nt = 0; nt < 4; nt++) {
                #pragma unroll
                for (int cb = 0; cb < 2; cb++) {
                    int nl = wn * 32 + nt * 8 + v * 2 + cb;
                    float d2 = fmaxf(fmaf(-2.f, acc[mt][nt][rh * 2 + cb],
                                          sqi + s_sqj[nl]), 0.f);
                    int ci = nt * 2 + cb;
                    if (li == s_lj[nl]) {
                        apv = fmaxf(apv, d2);
                        ap_c[ci] = fmaxf(ap_c[ci], d2);
                    } else {
                        anv = fminf(anv, d2);
                        an_c[ci] = fminf(an_c[ci], d2);
                    }
                }
            }
            ap_r[ri] = apv; an_r[ri] = anv;
        }
    }

    const unsigned FM = 0xffffffffu;
    #pragma unroll
    for (int i = 0; i < 8; i++) {          // reduce over v (4 col-lanes)
        float ap = ap_r[i], an = an_r[i];
        ap = fmaxf(ap, __shfl_xor_sync(FM, ap, 1));
        ap = fmaxf(ap, __shfl_xor_sync(FM, ap, 2));
        an = fminf(an, __shfl_xor_sync(FM, an, 1));
        an = fminf(an, __shfl_xor_sync(FM, an, 2));
        if (v == 0) {
            int ml = wm * 64 + (i >> 1) * 16 + u + (i & 1) * 8;
            atomicMax(&s_ap_r[ml], __float_as_int(ap));
            atomicMin(&s_an_r[ml], __float_as_int(an));
        }
    }
    #pragma unroll
    for (int i = 0; i < 8; i++) {          // reduce over u (8 row-lanes)
        float ap = ap_c[i], an = an_c[i];
        ap = fmaxf(ap, __shfl_xor_sync(FM, ap, 4));
        ap = fmaxf(ap, __shfl_xor_sync(FM, ap, 8));
        ap = fmaxf(ap, __shfl_xor_sync(FM, ap, 16));
        an = fminf(an, __shfl_xor_sync(FM, an, 4));
        an = fminf(an, __shfl_xor_sync(FM, an, 8));
        an = fminf(an, __shfl_xor_sync(FM, an, 16));
        if (u == 0) {
            int nl = wn * 32 + (i >> 1) * 8 + v * 2 + (i & 1);
            atomicMax(&s_ap_c[nl], __float_as_int(ap));
            atomicMin(&s_an_c[nl], __float_as_int(an));
        }
    }
    __syncthreads();

    if (tid < TM) {
        atomicMax(&g_ap[bi * TM + tid], s_ap_r[tid]);
        atomicMin(&g_an[bi * TM + tid], s_an_r[tid]);
    }
    if (tid < TN) {
        atomicMax(&g_ap[bj * TN + tid], s_ap_c[tid]);
        atomicMin(&g_an[bj * TN + tid], s_an_c[tid]);
    }
}

// ---------------------------------------------------------------------------
// Kernel 3: loss = mean(relu(margin + sqrt(ap2) - sqrt(an2)))
// ---------------------------------------------------------------------------
__global__ void __launch_bounds__(256) loss_kernel(float* __restrict__ out) {
    float s = 0.f;
    for (int i = threadIdx.x; i < NROWS; i += 256) {
        float ap = sqrtf(fmaxf(__int_as_float(g_ap[i]), 1e-12f));
        float an = sqrtf(fmaxf(__int_as_float(g_an[i]), 1e-12f));
        s += fmaxf(MARGIN_F + ap - an, 0.f);
    }
    __shared__ float red[8];
    #pragma unroll
    for (int o = 16; o; o >>= 1) s += __shfl_down_sync(0xffffffffu, s, o);
    if ((threadIdx.x & 31) == 0) red[threadIdx.x >> 5] = s;
    __syncthreads();
    if (threadIdx.x == 0) {
        float t = 0.f;
        #pragma unroll
        for (int w = 0; w < 8; w++) t += red[w];
        out[0] = t / (float)NROWS;
    }
}

extern "C" void kernel_launch(void* const* d_in, const int* in_sizes, int n_in,
                              void* d_out, int out_size) {
    const float* x  = (const float*)d_in[0];
    const int*   tg = (const int*)d_in[1];
    float* out = (float*)d_out;

    cudaFuncSetAttribute(dist_kernel, cudaFuncAttributeMaxDynamicSharedMemorySize, DYN_BYTES);

    prep_kernel<<<NROWS, 256>>>(x);
    dim3 grid(NROWS / TN, NROWS / TM);   // (16, 32): x=bj, y=bi
    dist_kernel<<<grid, NTHREADS, DYN_BYTES>>>(x, tg);
    loss_kernel<<<1, 256>>>(out);
}

// round 6
// speedup vs baseline: 4.4819x; 1.0819x over previous
#include <cuda_runtime.h>
#include <cstdint>

#define NROWS 4096
#define KDIM  2048
#define MARGIN_F 0.3f

#define TM 128
#define TN 256
#define KC 32
#define NCHUNK (KDIM / KC)          // 64
#define NTHREADS 512

#define A_BYTES (TM * KC * 4)       // 16384
#define B_BYTES (TN * KC * 4)       // 32768
#define STAGE_BYTES (A_BYTES + B_BYTES)   // 49152
#define NSTAGE 4
#define DYN_BYTES (NSTAGE * STAGE_BYTES + 1024)  // 197632 (incl. align slack)

__device__ float g_sq[NROWS];
__device__ int   g_ap[NROWS];   // d^2 bits (non-negative) -> int max/min valid
__device__ int   g_an[NROWS];

static __device__ __forceinline__ uint32_t smem_u32(const void* p) {
    uint32_t a;
    asm("{ .reg .u64 t; cvta.to.shared.u64 t, %1; cvt.u32.u64 %0, t; }" : "=r"(a) : "l"(p));
    return a;
}
static __device__ __forceinline__ void cp16(uint32_t s, const void* g) {
    asm volatile("cp.async.cg.shared.global [%0], [%1], 16;" :: "r"(s), "l"(g));
}
#define CP_COMMIT() asm volatile("cp.async.commit_group;" ::: "memory")
#define CP_WAIT2()  asm volatile("cp.async.wait_group 2;" ::: "memory")

static __device__ __forceinline__ void mma_tf32(float* d, const uint32_t* a, const uint32_t* b) {
    asm volatile(
        "mma.sync.aligned.m16n8k8.row.col.f32.tf32.tf32.f32 "
        "{%0,%1,%2,%3}, {%4,%5,%6,%7}, {%8,%9}, {%0,%1,%2,%3};"
        : "+f"(d[0]), "+f"(d[1]), "+f"(d[2]), "+f"(d[3])
        : "r"(a[0]), "r"(a[1]), "r"(a[2]), "r"(a[3]), "r"(b[0]), "r"(b[1]));
}
static __device__ __forceinline__ void ldsm4(uint32_t* r, uint32_t addr) {
    asm volatile("ldmatrix.sync.aligned.m8n8.x4.shared.b16 {%0,%1,%2,%3}, [%4];"
        : "=r"(r[0]), "=r"(r[1]), "=r"(r[2]), "=r"(r[3]) : "r"(addr));
}

// ---------------------------------------------------------------------------
// Kernel 1: squared norms per row + init of ap/an accumulators
// ---------------------------------------------------------------------------
__global__ void __launch_bounds__(256) prep_kernel(const float* __restrict__ x) {
    int row = blockIdx.x;
    const float4* xr = reinterpret_cast<const float4*>(x + (size_t)row * KDIM);
    float s = 0.f;
    for (int i = threadIdx.x; i < KDIM / 4; i += 256) {
        float4 v = xr[i];
        s += v.x * v.x + v.y * v.y + v.z * v.z + v.w * v.w;
    }
    __shared__ float red[8];
    #pragma unroll
    for (int o = 16; o; o >>= 1) s += __shfl_down_sync(0xffffffffu, s, o);
    if ((threadIdx.x & 31) == 0) red[threadIdx.x >> 5] = s;
    __syncthreads();
    if (threadIdx.x == 0) {
        float t = 0.f;
        #pragma unroll
        for (int w = 0; w < 8; w++) t += red[w];
        g_sq[row] = t;
        g_ap[row] = 0;
        g_an[row] = 0x7f800000;
    }
}

// ---------------------------------------------------------------------------
// Kernel 2: tf32 mma.sync Gram tile (128x256), 16 warps, 4-stage cp.async,
// ldmatrix fragment loads (4x fewer smem issues). Upper-triangle tiles only;
// epilogue compares d^2 (sqrt deferred), row- and col-side reductions.
// ---------------------------------------------------------------------------
__global__ void __launch_bounds__(NTHREADS, 1)
dist_kernel(const float* __restrict__ x, const int* __restrict__ tg) {
    int bi = blockIdx.y, bj = blockIdx.x;
    if (bj < (bi >> 1)) return;   // tile fully below diagonal

    extern __shared__ char raw_dsm[];
    __shared__ int   s_ap_r[TM], s_an_r[TM];
    __shared__ int   s_ap_c[TN], s_an_c[TN];
    __shared__ float s_sqi[TM],  s_sqj[TN];
    __shared__ int   s_li[TM],   s_lj[TN];

    int tid = threadIdx.x, lid = tid & 31, wid = tid >> 5;
    int wm = wid >> 3, wn = wid & 7;       // 2 x 8 warp grid, warp tile 64x32
    int u = lid >> 2, v = lid & 3;
    int r8 = lid & 7, mq = lid >> 3;       // ldmatrix lane decomposition
    int mlow = mq & 1, mhigh = mq >> 1;

    uint32_t raw_base = smem_u32(raw_dsm);
    uint32_t sbase = (raw_base + 1023u) & ~1023u;

    const float* Ab = x + (size_t)(bi * TM) * KDIM;
    const float* Bb = x + (size_t)(bj * TN) * KDIM;

    if (tid < TM) {
        s_ap_r[tid] = 0; s_an_r[tid] = 0x7f800000;
        s_sqi[tid] = g_sq[bi * TM + tid];
        s_li[tid]  = tg[bi * TM + tid];
    }
    if (tid < TN) {
        s_ap_c[tid] = 0; s_an_c[tid] = 0x7f800000;
        s_sqj[tid] = g_sq[bj * TN + tid];
        s_lj[tid]  = tg[bj * TN + tid];
    }

    float acc[4][4][4];
    #pragma unroll
    for (int mt = 0; mt < 4; mt++)
        #pragma unroll
        for (int nt = 0; nt < 4; nt++)
            #pragma unroll
            for (int q = 0; q < 4; q++) acc[mt][nt][q] = 0.f;

    // ldmatrix per-lane bases (within a stage):
    //   A x4 tile (mt,kk): matrices {rows0-7,k0-3},{rows8-15,k0-3},{rows0-7,k4-7},{rows8-15,k4-7}
    //   lane addr: row = mt*16 + mlow*8 + r8 ; kbyte = kk*32 + mhigh*16 (XOR r8*16)
    uint32_t a_lane = (uint32_t)((wm * 64 + mlow * 8 + r8) * 128);
    //   B x4 tile (ntp,kk): {nt0,k0-3},{nt0,k4-7},{nt1,k0-3},{nt1,k4-7}
    //   lane addr: n = wn*32 + ntp*16 + mhigh*8 + r8 ; kbyte = kk*32 + mlow*16 (XOR r8*16)
    uint32_t b_lane = (uint32_t)A_BYTES + (uint32_t)((wn * 32 + mhigh * 8 + r8) * 128);
    uint32_t akx[4], bkx[4];
    #pragma unroll
    for (int kk = 0; kk < 4; kk++) {
        akx[kk] = (uint32_t)((kk * 32 + mhigh * 16) ^ (r8 * 16));
        bkx[kk] = (uint32_t)((kk * 32 + mlow  * 16) ^ (r8 * 16));
    }

    // swizzled 16B-unit staging: byte = r*128 + ((c4*16) ^ ((r&7)*16))
    #define STAGE(ic, s) do {                                                  \
        uint32_t b0_ = sbase + (uint32_t)(s) * STAGE_BYTES;                    \
        const float* Ak_ = Ab + (ic) * KC;                                     \
        const float* Bk_ = Bb + (ic) * KC;                                     \
        _Pragma("unroll")                                                      \
        for (int t = 0; t < 2; t++) {                                          \
            int idx = tid + t * NTHREADS; int r = idx >> 3, c4 = idx & 7;      \
            uint32_t sw = (uint32_t)(r * 128 + ((c4 * 16) ^ ((r & 7) * 16)));  \
            cp16(b0_ + sw, Ak_ + (size_t)r * KDIM + c4 * 4);                   \
        }                                                                      \
        _Pragma("unroll")                                                      \
        for (int t = 0; t < 4; t++) {                                          \
            int idx = tid + t * NTHREADS; int r = idx >> 3, c4 = idx & 7;      \
            uint32_t sw = (uint32_t)(r * 128 + ((c4 * 16) ^ ((r & 7) * 16)));  \
            cp16(b0_ + A_BYTES + sw, Bk_ + (size_t)r * KDIM + c4 * 4);         \
        }                                                                      \
    } while (0)

    STAGE(0, 0); CP_COMMIT();
    STAGE(1, 1); CP_COMMIT();
    STAGE(2, 2); CP_COMMIT();

    for (int ic = 0; ic < NCHUNK; ic++) {
        int s = ic & 3;
        CP_WAIT2();
        __syncthreads();

        uint32_t stg = sbase + (uint32_t)s * STAGE_BYTES;
        uint32_t a0 = stg + a_lane;
        uint32_t b0 = stg + b_lane;

        #pragma unroll
        for (int kk = 0; kk < 4; kk++) {
            uint32_t af[4][4], rb[2][4];
            #pragma unroll
            for (int mt = 0; mt < 4; mt++)
                ldsm4(af[mt], a0 + (uint32_t)(mt * 2048) + akx[kk]);
            #pragma unroll
            for (int ntp = 0; ntp < 2; ntp++)
                ldsm4(rb[ntp], b0 + (uint32_t)(ntp * 2048) + bkx[kk]);
            #pragma unroll
            for (int mt = 0; mt < 4; mt++) {
                #pragma unroll
                for (int ntp = 0; ntp < 2; ntp++) {
                    mma_tf32(acc[mt][ntp * 2 + 0], af[mt], &rb[ntp][0]);
                    mma_tf32(acc[mt][ntp * 2 + 1], af[mt], &rb[ntp][2]);
                }
            }
        }

        if (ic + 3 < NCHUNK) STAGE(ic + 3, (ic + 3) & 3);
        CP_COMMIT();
    }

    // ---- epilogue: d^2, masked hardest pos/neg, idempotent reductions ----
    const float INF = __int_as_float(0x7f800000);
    float ap_r[8], an_r[8], ap_c[8], an_c[8];
    #pragma unroll
    for (int i = 0; i < 8; i++) { ap_r[i] = 0.f; an_r[i] = INF; ap_c[i] = 0.f; an_c[i] = INF; }

    #pragma unroll
    for (int mt = 0; mt < 4; mt++) {
        #pragma unroll
        for (int rh = 0; rh < 2; rh++) {
            int ml = wm * 64 + mt * 16 + u + rh * 8;
            float sqi = s_sqi[ml];
            int   li  = s_li[ml];
            int ri = mt * 2 + rh;
            float apv = ap_r[ri], anv = an_r[ri];
            #pragma unroll
            for (int nt = 0; nt < 4; nt++) {
                #pragma unroll
                for (int cb = 0; cb < 2; cb++) {
                    int nl = wn * 32 + nt * 8 + v * 2 + cb;
                    float d2 = fmaxf(fmaf(-2.f, acc[mt][nt][rh * 2 + cb],
                                          sqi + s_sqj[nl]), 0.f);
                    int ci = nt * 2 + cb;
                    if (li == s_lj[nl]) {
                        apv = fmaxf(apv, d2);
                        ap_c[ci] = fmaxf(ap_c[ci], d2);
                    } else {
                        anv = fminf(anv, d2);
                        an_c[ci] = fminf(an_c[ci], d2);
                    }
                }
            }
            ap_r[ri] = apv; an_r[ri] = anv;
        }
    }

    const unsigned FM = 0xffffffffu;
    #pragma unroll
    for (int i = 0; i < 8; i++) {          // reduce over v (4 col-lanes)
        float ap = ap_r[i], an = an_r[i];
        ap = fmaxf(ap, __shfl_xor_sync(FM, ap, 1));
        ap = fmaxf(ap, __shfl_xor_sync(FM, ap, 2));
        an = fminf(an, __shfl_xor_sync(FM, an, 1));
        an = fminf(an, __shfl_xor_sync(FM, an, 2));
        if (v == 0) {
            int ml = wm * 64 + (i >> 1) * 16 + u + (i & 1) * 8;
            atomicMax(&s_ap_r[ml], __float_as_int(ap));
            atomicMin(&s_an_r[ml], __float_as_int(an));
        }
    }
    #pragma unroll
    for (int i = 0; i < 8; i++) {          // reduce over u (8 row-lanes)
        float ap = ap_c[i], an = an_c[i];
        ap = fmaxf(ap, __shfl_xor_sync(FM, ap, 4));
        ap = fmaxf(ap, __shfl_xor_sync(FM, ap, 8));
        ap = fmaxf(ap, __shfl_xor_sync(FM, ap, 16));
        an = fminf(an, __shfl_xor_sync(FM, an, 4));
        an = fminf(an, __shfl_xor_sync(FM, an, 8));
        an = fminf(an, __shfl_xor_sync(FM, an, 16));
        if (u == 0) {
            int nl = wn * 32 + (i >> 1) * 8 + v * 2 + (i & 1);
            atomicMax(&s_ap_c[nl], __float_as_int(ap));
            atomicMin(&s_an_c[nl], __float_as_int(an));
        }
    }
    __syncthreads();

    if (tid < TM) {
        atomicMax(&g_ap[bi * TM + tid], s_ap_r[tid]);
        atomicMin(&g_an[bi * TM + tid], s_an_r[tid]);
    }
    if (tid < TN) {
        atomicMax(&g_ap[bj * TN + tid], s_ap_c[tid]);
        atomicMin(&g_an[bj * TN + tid], s_an_c[tid]);
    }
}

// ---------------------------------------------------------------------------
// Kernel 3: loss = mean(relu(margin + sqrt(ap2) - sqrt(an2)))
// ---------------------------------------------------------------------------
__global__ void __launch_bounds__(256) loss_kernel(float* __restrict__ out) {
    float s = 0.f;
    for (int i = threadIdx.x; i < NROWS; i += 256) {
        float ap = sqrtf(fmaxf(__int_as_float(g_ap[i]), 1e-12f));
        float an = sqrtf(fmaxf(__int_as_float(g_an[i]), 1e-12f));
        s += fmaxf(MARGIN_F + ap - an, 0.f);
    }
    __shared__ float red[8];
    #pragma unroll
    for (int o = 16; o; o >>= 1) s += __shfl_down_sync(0xffffffffu, s, o);
    if ((threadIdx.x & 31) == 0) red[threadIdx.x >> 5] = s;
    __syncthreads();
    if (threadIdx.x == 0) {
        float t = 0.f;
        #pragma unroll
        for (int w = 0; w < 8; w++) t += red[w];
        out[0] = t / (float)NROWS;
    }
}

extern "C" void kernel_launch(void* const* d_in, const int* in_sizes, int n_in,
                              void* d_out, int out_size) {
    const float* x  = (const float*)d_in[0];
    const int*   tg = (const int*)d_in[1];
    float* out = (float*)d_out;

    cudaFuncSetAttribute(dist_kernel, cudaFuncAttributeMaxDynamicSharedMemorySize, DYN_BYTES);

    prep_kernel<<<NROWS, 256>>>(x);
    dim3 grid(NROWS / TN, NROWS / TM);   // (16, 32): x=bj, y=bi
    dist_kernel<<<grid, NTHREADS, DYN_BYTES>>>(x, tg);
    loss_kernel<<<1, 256>>>(out);
}

// round 7
// speedup vs baseline: 7.7960x; 1.7394x over previous
#include <cuda_runtime.h>
#include <cuda_fp16.h>
#include <cstdint>

#define NROWS 4096
#define KDIM  2048
#define MARGIN_F 0.3f

#define TM 128
#define TN 256
#define KC 64                        // f16 k-chunk: 128 bytes per row
#define NCHUNK (KDIM / KC)           // 32
#define NTHREADS 512

#define A_BYTES (TM * KC * 2)        // 16384
#define B_BYTES (TN * KC * 2)        // 32768
#define STAGE_BYTES (A_BYTES + B_BYTES)   // 49152
#define NSTAGE 4
#define DYN_BYTES (NSTAGE * STAGE_BYTES + 1024)  // 197632

__device__ float  g_sq[NROWS];
__device__ int    g_ap[NROWS];   // d^2 bits (non-negative) -> int max/min valid
__device__ int    g_an[NROWS];
__device__ __half g_xh[NROWS * KDIM];   // fp16 copy of inputs (16 MB)

static __device__ __forceinline__ uint32_t smem_u32(const void* p) {
    uint32_t a;
    asm("{ .reg .u64 t; cvta.to.shared.u64 t, %1; cvt.u32.u64 %0, t; }" : "=r"(a) : "l"(p));
    return a;
}
static __device__ __forceinline__ void cp16(uint32_t s, const void* g) {
    asm volatile("cp.async.cg.shared.global [%0], [%1], 16;" :: "r"(s), "l"(g));
}
#define CP_COMMIT() asm volatile("cp.async.commit_group;" ::: "memory")
#define CP_WAIT2()  asm volatile("cp.async.wait_group 2;" ::: "memory")

static __device__ __forceinline__ void mma_f16(float* d, const uint32_t* a, const uint32_t* b) {
    asm volatile(
        "mma.sync.aligned.m16n8k16.row.col.f32.f16.f16.f32 "
        "{%0,%1,%2,%3}, {%4,%5,%6,%7}, {%8,%9}, {%0,%1,%2,%3};"
        : "+f"(d[0]), "+f"(d[1]), "+f"(d[2]), "+f"(d[3])
        : "r"(a[0]), "r"(a[1]), "r"(a[2]), "r"(a[3]), "r"(b[0]), "r"(b[1]));
}
static __device__ __forceinline__ void ldsm4(uint32_t* r, uint32_t addr) {
    asm volatile("ldmatrix.sync.aligned.m8n8.x4.shared.b16 {%0,%1,%2,%3}, [%4];"
        : "=r"(r[0]), "=r"(r[1]), "=r"(r[2]), "=r"(r[3]) : "r"(addr));
}

// ---------------------------------------------------------------------------
// Kernel 1: squared norms + init accumulators + fp16 copy of the input
// ---------------------------------------------------------------------------
__global__ void __launch_bounds__(256) prep_kernel(const float* __restrict__ x) {
    int row = blockIdx.x;
    const float4* xr = reinterpret_cast<const float4*>(x + (size_t)row * KDIM);
    uint2* xh = reinterpret_cast<uint2*>(g_xh + (size_t)row * KDIM);
    float s = 0.f;
    for (int i = threadIdx.x; i < KDIM / 4; i += 256) {
        float4 v = xr[i];
        s += v.x * v.x + v.y * v.y + v.z * v.z + v.w * v.w;
        __half2 h0 = __floats2half2_rn(v.x, v.y);
        __half2 h1 = __floats2half2_rn(v.z, v.w);
        uint2 hp;
        hp.x = *reinterpret_cast<uint32_t*>(&h0);
        hp.y = *reinterpret_cast<uint32_t*>(&h1);
        xh[i] = hp;
    }
    __shared__ float red[8];
    #pragma unroll
    for (int o = 16; o; o >>= 1) s += __shfl_down_sync(0xffffffffu, s, o);
    if ((threadIdx.x & 31) == 0) red[threadIdx.x >> 5] = s;
    __syncthreads();
    if (threadIdx.x == 0) {
        float t = 0.f;
        #pragma unroll
        for (int w = 0; w < 8; w++) t += red[w];
        g_sq[row] = t;
        g_ap[row] = 0;
        g_an[row] = 0x7f800000;
    }
}

// ---------------------------------------------------------------------------
// Kernel 2: fp16 mma.sync Gram tile (128x256), 16 warps, 4-stage cp.async,
// ldmatrix fragments. fp16 k16 halves HMMA instruction count vs tf32 k8 at
// the same 11-bit significand. Upper-triangle tiles only; epilogue on d^2.
// ---------------------------------------------------------------------------
__global__ void __launch_bounds__(NTHREADS, 1)
dist_kernel(const int* __restrict__ tg) {
    int bi = blockIdx.y, bj = blockIdx.x;
    if (bj < (bi >> 1)) return;   // tile fully below diagonal

    extern __shared__ char raw_dsm[];
    __shared__ int   s_ap_r[TM], s_an_r[TM];
    __shared__ int   s_ap_c[TN], s_an_c[TN];
    __shared__ float s_sqi[TM],  s_sqj[TN];
    __shared__ int   s_li[TM],   s_lj[TN];

    int tid = threadIdx.x, lid = tid & 31, wid = tid >> 5;
    int wm = wid >> 3, wn = wid & 7;       // 2 x 8 warp grid, warp tile 64x32
    int u = lid >> 2, v = lid & 3;
    int r8 = lid & 7, mq = lid >> 3;       // ldmatrix lane decomposition
    int mlow = mq & 1, mhigh = mq >> 1;

    uint32_t raw_base = smem_u32(raw_dsm);
    uint32_t sbase = (raw_base + 1023u) & ~1023u;

    const __half* Ab = g_xh + (size_t)(bi * TM) * KDIM;
    const __half* Bb = g_xh + (size_t)(bj * TN) * KDIM;

    if (tid < TM) {
        s_ap_r[tid] = 0; s_an_r[tid] = 0x7f800000;
        s_sqi[tid] = g_sq[bi * TM + tid];
        s_li[tid]  = tg[bi * TM + tid];
    }
    if (tid < TN) {
        s_ap_c[tid] = 0; s_an_c[tid] = 0x7f800000;
        s_sqj[tid] = g_sq[bj * TN + tid];
        s_lj[tid]  = tg[bj * TN + tid];
    }

    float acc[4][4][4];
    #pragma unroll
    for (int mt = 0; mt < 4; mt++)
        #pragma unroll
        for (int nt = 0; nt < 4; nt++)
            #pragma unroll
            for (int q = 0; q < 4; q++) acc[mt][nt][q] = 0.f;

    // ldmatrix lane bases: 128B rows (64 f16), 16B-unit XOR swizzle.
    // A x4 (mt, ks): {m-lo,k-lo16B},{m-hi,k-lo},{m-lo,k-hi},{m-hi,k-hi} = f16 a0..a3
    uint32_t a_lane = (uint32_t)((wm * 64 + mlow * 8 + r8) * 128);
    // B x4 (ntp, ks): {n-lo,k-lo},{n-lo,k-hi},{n-hi,k-lo},{n-hi,k-hi} -> b pairs {r0,r1},{r2,r3}
    uint32_t b_lane = (uint32_t)A_BYTES + (uint32_t)((wn * 32 + mhigh * 8 + r8) * 128);
    uint32_t akx[4], bkx[4];
    #pragma unroll
    for (int ks = 0; ks < 4; ks++) {
        akx[ks] = (uint32_t)((ks * 32 + mhigh * 16) ^ (r8 * 16));
        bkx[ks] = (uint32_t)((ks * 32 + mlow  * 16) ^ (r8 * 16));
    }

    // staging: f16 rows, 128B/row = 8 x 16B units; byte = r*128 + ((c4*16) ^ ((r&7)*16))
    #define STAGE(ic, s) do {                                                  \
        uint32_t b0_ = sbase + (uint32_t)(s) * STAGE_BYTES;                    \
        const __half* Ak_ = Ab + (ic) * KC;                                    \
        const __half* Bk_ = Bb + (ic) * KC;                                    \
        _Pragma("unroll")                                                      \
        for (int t = 0; t < 2; t++) {                                          \
            int idx = tid + t * NTHREADS; int r = idx >> 3, c4 = idx & 7;      \
            uint32_t sw = (uint32_t)(r * 128 + ((c4 * 16) ^ ((r & 7) * 16)));  \
            cp16(b0_ + sw, Ak_ + (size_t)r * KDIM + c4 * 8);                   \
        }                                                                      \
        _Pragma("unroll")                                                      \
        for (int t = 0; t < 4; t++) {                                          \
            int idx = tid + t * NTHREADS; int r = idx >> 3, c4 = idx & 7;      \
            uint32_t sw = (uint32_t)(r * 128 + ((c4 * 16) ^ ((r & 7) * 16)));  \
            cp16(b0_ + A_BYTES + sw, Bk_ + (size_t)r * KDIM + c4 * 8);         \
        }                                                                      \
    } while (0)

    STAGE(0, 0); CP_COMMIT();
    STAGE(1, 1); CP_COMMIT();
    STAGE(2, 2); CP_COMMIT();

    for (int ic = 0; ic < NCHUNK; ic++) {
        int s = ic & 3;
        CP_WAIT2();
        __syncthreads();

        uint32_t stg = sbase + (uint32_t)s * STAGE_BYTES;
        uint32_t a0 = stg + a_lane;
        uint32_t b0 = stg + b_lane;

        #pragma unroll
        for (int ks = 0; ks < 4; ks++) {
            uint32_t af[4][4], rb[2][4];
            #pragma unroll
            for (int mt = 0; mt < 4; mt++)
                ldsm4(af[mt], a0 + (uint32_t)(mt * 2048) + akx[ks]);
            #pragma unroll
            for (int ntp = 0; ntp < 2; ntp++)
                ldsm4(rb[ntp], b0 + (uint32_t)(ntp * 2048) + bkx[ks]);
            #pragma unroll
            for (int mt = 0; mt < 4; mt++) {
                #pragma unroll
                for (int ntp = 0; ntp < 2; ntp++) {
                    mma_f16(acc[mt][ntp * 2 + 0], af[mt], &rb[ntp][0]);
                    mma_f16(acc[mt][ntp * 2 + 1], af[mt], &rb[ntp][2]);
                }
            }
        }

        if (ic + 3 < NCHUNK) STAGE(ic + 3, (ic + 3) & 3);
        CP_COMMIT();
    }

    // ---- epilogue: d^2, masked hardest pos/neg, idempotent reductions ----
    const float INF = __int_as_float(0x7f800000);
    float ap_r[8], an_r[8], ap_c[8], an_c[8];
    #pragma unroll
    for (int i = 0; i < 8; i++) { ap_r[i] = 0.f; an_r[i] = INF; ap_c[i] = 0.f; an_c[i] = INF; }

    #pragma unroll
    for (int mt = 0; mt < 4; mt++) {
        #pragma unroll
        for (int rh = 0; rh < 2; rh++) {
            int ml = wm * 64 + mt * 16 + u + rh * 8;
            float sqi = s_sqi[ml];
            int   li  = s_li[ml];
            int ri = mt * 2 + rh;
            float apv = ap_r[ri], anv = an_r[ri];
            #pragma unroll
            for (int nt = 0; nt < 4; nt++) {
                #pragma unroll
                for (int cb = 0; cb < 2; cb++) {
                    int nl = wn * 32 + nt * 8 + v * 2 + cb;
                    float d2 = fmaxf(fmaf(-2.f, acc[mt][nt][rh * 2 + cb],
                                          sqi + s_sqj[nl]), 0.f);
                    int ci = nt * 2 + cb;
                    if (li == s_lj[nl]) {
                        apv = fmaxf(apv, d2);
                        ap_c[ci] = fmaxf(ap_c[ci], d2);
                    } else {
                        anv = fminf(anv, d2);
                        an_c[ci] = fminf(an_c[ci], d2);
                    }
                }
            }
            ap_r[ri] = apv; an_r[ri] = anv;
        }
    }

    const unsigned FM = 0xffffffffu;
    #pragma unroll
    for (int i = 0; i < 8; i++) {          // reduce over v (4 col-lanes)
        float ap = ap_r[i], an = an_r[i];
        ap = fmaxf(ap, __shfl_xor_sync(FM, ap, 1));
        ap = fmaxf(ap, __shfl_xor_sync(FM, ap, 2));
        an = fminf(an, __shfl_xor_sync(FM, an, 1));
        an = fminf(an, __shfl_xor_sync(FM, an, 2));
        if (v == 0) {
            int ml = wm * 64 + (i >> 1) * 16 + u + (i & 1) * 8;
            atomicMax(&s_ap_r[ml], __float_as_int(ap));
            atomicMin(&s_an_r[ml], __float_as_int(an));
        }
    }
    #pragma unroll
    for (int i = 0; i < 8; i++) {          // reduce over u (8 row-lanes)
        float ap = ap_c[i], an = an_c[i];
        ap = fmaxf(ap, __shfl_xor_sync(FM, ap, 4));
        ap = fmaxf(ap, __shfl_xor_sync(FM, ap, 8));
        ap = fmaxf(ap, __shfl_xor_sync(FM, ap, 16));
        an = fminf(an, __shfl_xor_sync(FM, an, 4));
        an = fminf(an, __shfl_xor_sync(FM, an, 8));
        an = fminf(an, __shfl_xor_sync(FM, an, 16));
        if (u == 0) {
            int nl = wn * 32 + (i >> 1) * 8 + v * 2 + (i & 1);
            atomicMax(&s_ap_c[nl], __float_as_int(ap));
            atomicMin(&s_an_c[nl], __float_as_int(an));
        }
    }
    __syncthreads();

    if (tid < TM) {
        atomicMax(&g_ap[bi * TM + tid], s_ap_r[tid]);
        atomicMin(&g_an[bi * TM + tid], s_an_r[tid]);
    }
    if (tid < TN) {
        atomicMax(&g_ap[bj * TN + tid], s_ap_c[tid]);
        atomicMin(&g_an[bj * TN + tid], s_an_c[tid]);
    }
}

// ---------------------------------------------------------------------------
// Kernel 3: loss = mean(relu(margin + sqrt(ap2) - sqrt(an2)))
// ---------------------------------------------------------------------------
__global__ void __launch_bounds__(256) loss_kernel(float* __restrict__ out) {
    float s = 0.f;
    for (int i = threadIdx.x; i < NROWS; i += 256) {
        float ap = sqrtf(fmaxf(__int_as_float(g_ap[i]), 1e-12f));
        float an = sqrtf(fmaxf(__int_as_float(g_an[i]), 1e-12f));
        s += fmaxf(MARGIN_F + ap - an, 0.f);
    }
    __shared__ float red[8];
    #pragma unroll
    for (int o = 16; o; o >>= 1) s += __shfl_down_sync(0xffffffffu, s, o);
    if ((threadIdx.x & 31) == 0) red[threadIdx.x >> 5] = s;
    __syncthreads();
    if (threadIdx.x == 0) {
        float t = 0.f;
        #pragma unroll
        for (int w = 0; w < 8; w++) t += red[w];
        out[0] = t / (float)NROWS;
    }
}

extern "C" void kernel_launch(void* const* d_in, const int* in_sizes, int n_in,
                              void* d_out, int out_size) {
    const float* x  = (const float*)d_in[0];
    const int*   tg = (const int*)d_in[1];
    float* out = (float*)d_out;

    cudaFuncSetAttribute(dist_kernel, cudaFuncAttributeMaxDynamicSharedMemorySize, DYN_BYTES);

    prep_kernel<<<NROWS, 256>>>(x);
    dim3 grid(NROWS / TN, NROWS / TM);   // (16, 32): x=bj, y=bi
    dist_kernel<<<grid, NTHREADS, DYN_BYTES>>>(tg);
    loss_kernel<<<1, 256>>>(out);
}